// round 1
// baseline (speedup 1.0000x reference)
#include <cuda_runtime.h>
#include <cuda_bf16.h>

// Problem constants (fixed by setup_inputs)
#define BB     4
#define NN     8192
#define CC     256
#define POOLN  2048      // NN / POOLING_RATE
#define NBR    4         // NEIGHBOR_NUM

// One warp per (batch, sampled point).
// Phase 1: ascending-index ball-query scan with early exit (ballot + ffs).
// Phase 2: coalesced gather of the (up to) 4 neighbor feature rows, max-reduce, store.
__global__ void pool_layer_kernel(const float* __restrict__ verts,     // [B, N, 3]
                                  const float* __restrict__ feat,      // [B, N, C]
                                  const int*   __restrict__ radius_raw,// [1] (int or float bits)
                                  const int*   __restrict__ sample_idx,// [POOLN]
                                  float* __restrict__ outV,            // [B, POOLN, 3]
                                  float* __restrict__ outF)            // [B, POOLN, C]
{
    const int warp = (blockIdx.x * blockDim.x + threadIdx.x) >> 5;
    const int lane = threadIdx.x & 31;
    if (warp >= BB * POOLN) return;

    const int b = warp / POOLN;
    const int s = warp - b * POOLN;
    const int n = sample_idx[s];

    // Decode radius: exponent bits set -> it was stored as float; else plain int.
    const unsigned rv = (unsigned)radius_raw[0];
    const float radius = (rv & 0x7F800000u) ? __int_as_float((int)rv) : (float)(int)rv;
    const float r2 = radius * radius;

    const float* vb = verts + (size_t)b * NN * 3;

    // Query point
    const float qx = vb[n * 3 + 0];
    const float qy = vb[n * 3 + 1];
    const float qz = vb[n * 3 + 2];
    const float sqn = qx * qx + qy * qy + qz * qz;

    // ---- Phase 1: find first NBR ascending indices with dist <= r^2 ----
    int idx[NBR];
    #pragma unroll
    for (int k = 0; k < NBR; k++) idx[k] = n;   // safe default (self always qualifies)
    int cnt = 0;

    for (int base = 0; base < NN; base += 32) {
        const int m = base + lane;
        const float vx = vb[m * 3 + 0];
        const float vy = vb[m * 3 + 1];
        const float vz = vb[m * 3 + 2];
        const float dot = vx * qx + vy * qy + vz * qz;
        const float sqm = vx * vx + vy * vy + vz * vz;
        // reference: dist = -2*dot + sq_n + sq_m ; included iff !(dist > r2)
        const float d = -2.0f * dot + sqn + sqm;
        const bool ok = !(d > r2);

        unsigned bal = __ballot_sync(0xFFFFFFFFu, ok);
        while (bal && cnt < NBR) {
            const int bit = __ffs(bal) - 1;
            idx[cnt++] = base + bit;
            bal &= bal - 1;
        }
        if (cnt >= NBR) break;   // uniform across warp (ballot-derived)
    }
    // Fill remainder with first found (matches reference's group_first fill)
    const int first = idx[0];
    #pragma unroll
    for (int k = 1; k < NBR; k++) if (k >= cnt) idx[k] = first;

    // ---- Phase 2: gather 4 feature rows, elementwise max, store ----
    const float* fb = feat + (size_t)b * NN * CC;
    const float* __restrict__ f0 = fb + (size_t)idx[0] * CC;
    const float* __restrict__ f1 = fb + (size_t)idx[1] * CC;
    const float* __restrict__ f2 = fb + (size_t)idx[2] * CC;
    const float* __restrict__ f3 = fb + (size_t)idx[3] * CC;
    float* __restrict__ fo = outF + ((size_t)b * POOLN + s) * CC;

    #pragma unroll
    for (int j = 0; j < CC / 32; j++) {
        const int c = lane + j * 32;
        float v = f0[c];
        v = fmaxf(v, f1[c]);
        v = fmaxf(v, f2[c]);
        v = fmaxf(v, f3[c]);
        fo[c] = v;
    }

    // ---- vertices_pool ----
    if (lane < 3) {
        outV[((size_t)b * POOLN + s) * 3 + lane] = vb[n * 3 + lane];
    }
}

extern "C" void kernel_launch(void* const* d_in, const int* in_sizes, int n_in,
                              void* d_out, int out_size)
{
    const float* verts      = (const float*)d_in[0];
    const float* feat       = (const float*)d_in[1];
    const int*   radius_raw = (const int*)  d_in[2];
    const int*   sample_idx = (const int*)  d_in[3];

    float* outV = (float*)d_out;                          // [B, POOLN, 3]
    float* outF = (float*)d_out + (size_t)BB * POOLN * 3; // [B, POOLN, C]

    const int total_warps = BB * POOLN;          // 8192
    const int threads = 256;                     // 8 warps / block
    const int blocks = (total_warps * 32 + threads - 1) / threads;  // 1024

    pool_layer_kernel<<<blocks, threads>>>(verts, feat, radius_raw, sample_idx,
                                           outV, outF);
}

// round 2
// speedup vs baseline: 1.0343x; 1.0343x over previous
#include <cuda_runtime.h>
#include <cuda_bf16.h>

// Problem constants (fixed by setup_inputs)
#define BB     4
#define NN     8192
#define CC     256
#define POOLN  2048      // NN / POOLING_RATE
#define NBR    4         // NEIGHBOR_NUM

// Packed vertices: (x, y, z, |v|^2) per point, coalesced 16B loads in the scan.
__device__ float4 g_pack[BB * NN];   // 512 KB device scratch (allowed)

__global__ void pack_kernel(const float* __restrict__ verts)
{
    const int i = blockIdx.x * blockDim.x + threadIdx.x;
    if (i >= BB * NN) return;
    const float x = verts[i * 3 + 0];
    const float y = verts[i * 3 + 1];
    const float z = verts[i * 3 + 2];
    g_pack[i] = make_float4(x, y, z, x * x + y * y + z * z);
}

// One warp per (batch, sampled point).
// Phase 1: ascending ball-query scan, 128 points/iteration (4 independent
//          LDG.128 + 4 independent ballots in flight) with early exit.
// Phase 2: float4 gather of 4 neighbor feature rows, max, store.
__global__ void pool_layer_kernel(const float* __restrict__ feat,      // [B, N, C]
                                  const int*   __restrict__ radius_raw,// [1]
                                  const int*   __restrict__ sample_idx,// [POOLN]
                                  float* __restrict__ outV,            // [B, POOLN, 3]
                                  float* __restrict__ outF)            // [B, POOLN, C]
{
    const int warp = (blockIdx.x * blockDim.x + threadIdx.x) >> 5;
    const int lane = threadIdx.x & 31;
    if (warp >= BB * POOLN) return;

    const int b = warp / POOLN;
    const int s = warp - b * POOLN;
    const int n = sample_idx[s];

    // Decode radius: exponent bits set -> float bits; else plain int.
    const unsigned rv = (unsigned)radius_raw[0];
    const float radius = (rv & 0x7F800000u) ? __int_as_float((int)rv) : (float)(int)rv;
    const float r2 = radius * radius;

    const float4* __restrict__ pb = g_pack + b * NN;

    // Query point
    const float4 q = pb[n];
    const float qx = q.x, qy = q.y, qz = q.z;
    const float sqn = qx * qx + qy * qy + qz * qz;   // same expression as reference path

    // ---- Phase 1: first NBR ascending indices with dist <= r^2 ----
    int idx[NBR];
    #pragma unroll
    for (int k = 0; k < NBR; k++) idx[k] = n;   // self always qualifies (d == ~0)
    int cnt = 0;

    for (int base = 0; base < NN; base += 128) {
        const float4 p0 = pb[base +  0 + lane];
        const float4 p1 = pb[base + 32 + lane];
        const float4 p2 = pb[base + 64 + lane];
        const float4 p3 = pb[base + 96 + lane];

        const float d0 = -2.0f * (p0.x * qx + p0.y * qy + p0.z * qz) + sqn
                         + (p0.x * p0.x + p0.y * p0.y + p0.z * p0.z);
        const float d1 = -2.0f * (p1.x * qx + p1.y * qy + p1.z * qz) + sqn
                         + (p1.x * p1.x + p1.y * p1.y + p1.z * p1.z);
        const float d2 = -2.0f * (p2.x * qx + p2.y * qy + p2.z * qz) + sqn
                         + (p2.x * p2.x + p2.y * p2.y + p2.z * p2.z);
        const float d3 = -2.0f * (p3.x * qx + p3.y * qy + p3.z * qz) + sqn
                         + (p3.x * p3.x + p3.y * p3.y + p3.z * p3.z);

        unsigned bal[4];
        bal[0] = __ballot_sync(0xFFFFFFFFu, !(d0 > r2));
        bal[1] = __ballot_sync(0xFFFFFFFFu, !(d1 > r2));
        bal[2] = __ballot_sync(0xFFFFFFFFu, !(d2 > r2));
        bal[3] = __ballot_sync(0xFFFFFFFFu, !(d3 > r2));

        #pragma unroll
        for (int t = 0; t < 4; t++) {
            unsigned m = bal[t];
            while (m && cnt < NBR) {
                idx[cnt++] = base + t * 32 + (__ffs(m) - 1);
                m &= m - 1;
            }
        }
        if (cnt >= NBR) break;   // uniform (ballot-derived)
    }
    const int first = idx[0];
    #pragma unroll
    for (int k = 1; k < NBR; k++) if (k >= cnt) idx[k] = first;

    // ---- Phase 2: gather 4 feature rows (float4), max, store ----
    const float* fb = feat + (size_t)b * NN * CC;
    const float4* __restrict__ f0 = (const float4*)(fb + (size_t)idx[0] * CC);
    const float4* __restrict__ f1 = (const float4*)(fb + (size_t)idx[1] * CC);
    const float4* __restrict__ f2 = (const float4*)(fb + (size_t)idx[2] * CC);
    const float4* __restrict__ f3 = (const float4*)(fb + (size_t)idx[3] * CC);
    float4* __restrict__ fo = (float4*)(outF + ((size_t)b * POOLN + s) * CC);

    #pragma unroll
    for (int j = 0; j < CC / 128; j++) {         // 256 floats = 64 float4 / 32 lanes = 2 iters
        const int c = lane + j * 32;
        float4 a = f0[c];
        const float4 v1 = f1[c];
        const float4 v2 = f2[c];
        const float4 v3 = f3[c];
        a.x = fmaxf(fmaxf(a.x, v1.x), fmaxf(v2.x, v3.x));
        a.y = fmaxf(fmaxf(a.y, v1.y), fmaxf(v2.y, v3.y));
        a.z = fmaxf(fmaxf(a.z, v1.z), fmaxf(v2.z, v3.z));
        a.w = fmaxf(fmaxf(a.w, v1.w), fmaxf(v2.w, v3.w));
        fo[c] = a;
    }

    // ---- vertices_pool (exact copy of packed coords) ----
    if (lane < 3) {
        const float v = (lane == 0) ? qx : (lane == 1) ? qy : qz;
        outV[((size_t)b * POOLN + s) * 3 + lane] = v;
    }
}

extern "C" void kernel_launch(void* const* d_in, const int* in_sizes, int n_in,
                              void* d_out, int out_size)
{
    const float* verts      = (const float*)d_in[0];
    const float* feat       = (const float*)d_in[1];
    const int*   radius_raw = (const int*)  d_in[2];
    const int*   sample_idx = (const int*)  d_in[3];

    float* outV = (float*)d_out;                          // [B, POOLN, 3]
    float* outF = (float*)d_out + (size_t)BB * POOLN * 3; // [B, POOLN, C]

    pack_kernel<<<(BB * NN + 255) / 256, 256>>>(verts);

    const int total_warps = BB * POOLN;          // 8192
    const int threads = 256;                     // 8 warps / block
    const int blocks = (total_warps * 32 + threads - 1) / threads;  // 1024

    pool_layer_kernel<<<blocks, threads>>>(feat, radius_raw, sample_idx, outV, outF);
}

// round 3
// speedup vs baseline: 1.8050x; 1.7452x over previous
#include <cuda_runtime.h>
#include <cuda_bf16.h>

#define BB     4
#define NN     8192
#define CC     256
#define POOLN  2048
#define NBR    4
#define EASY_LIMIT 1024   // points scanned by the warp-per-query pass (8 iters of 128)

__device__ float4 g_pack[BB * NN];        // (x,y,z,|v|^2), L2-resident scratch
__device__ int    g_hard[BB * POOLN];     // 1 = needs cooperative rescan

__global__ void pack_kernel(const float* __restrict__ verts)
{
    const int i = blockIdx.x * blockDim.x + threadIdx.x;
    if (i >= BB * NN) return;
    const float x = verts[i * 3 + 0];
    const float y = verts[i * 3 + 1];
    const float z = verts[i * 3 + 2];
    g_pack[i] = make_float4(x, y, z, 0.0f);
}

__device__ __forceinline__ float decode_radius(const int* radius_raw)
{
    const unsigned rv = (unsigned)radius_raw[0];
    return (rv & 0x7F800000u) ? __int_as_float((int)rv) : (float)(int)rv;
}

// ---------------- Kernel 1: warp per query, bounded scan ----------------
__global__ __launch_bounds__(256)
void pool_easy_kernel(const float* __restrict__ feat,
                      const int*   __restrict__ radius_raw,
                      const int*   __restrict__ sample_idx,
                      float* __restrict__ outV,
                      float* __restrict__ outF)
{
    const int warp = (blockIdx.x * blockDim.x + threadIdx.x) >> 5;
    const int lane = threadIdx.x & 31;
    if (warp >= BB * POOLN) return;

    const int b = warp / POOLN;
    const int s = warp - b * POOLN;
    const int n = sample_idx[s];

    const float radius = decode_radius(radius_raw);
    const float r2 = radius * radius;

    const float4* __restrict__ pb = g_pack + b * NN;
    const float4 q = pb[n];
    const float qx = q.x, qy = q.y, qz = q.z;
    const float sqn = qx * qx + qy * qy + qz * qz;

    // vertices_pool (always)
    if (lane < 3) {
        const float v = (lane == 0) ? qx : (lane == 1) ? qy : qz;
        outV[((size_t)b * POOLN + s) * 3 + lane] = v;
    }

    int idx[NBR];
    #pragma unroll
    for (int k = 0; k < NBR; k++) idx[k] = n;
    int cnt = 0;

    for (int base = 0; base < EASY_LIMIT; base += 128) {
        const float4 p0 = pb[base +  0 + lane];
        const float4 p1 = pb[base + 32 + lane];
        const float4 p2 = pb[base + 64 + lane];
        const float4 p3 = pb[base + 96 + lane];

        const float d0 = -2.0f*(p0.x*qx+p0.y*qy+p0.z*qz)+sqn+(p0.x*p0.x+p0.y*p0.y+p0.z*p0.z);
        const float d1 = -2.0f*(p1.x*qx+p1.y*qy+p1.z*qz)+sqn+(p1.x*p1.x+p1.y*p1.y+p1.z*p1.z);
        const float d2 = -2.0f*(p2.x*qx+p2.y*qy+p2.z*qz)+sqn+(p2.x*p2.x+p2.y*p2.y+p2.z*p2.z);
        const float d3 = -2.0f*(p3.x*qx+p3.y*qy+p3.z*qz)+sqn+(p3.x*p3.x+p3.y*p3.y+p3.z*p3.z);

        unsigned bal[4];
        bal[0] = __ballot_sync(0xFFFFFFFFu, !(d0 > r2));
        bal[1] = __ballot_sync(0xFFFFFFFFu, !(d1 > r2));
        bal[2] = __ballot_sync(0xFFFFFFFFu, !(d2 > r2));
        bal[3] = __ballot_sync(0xFFFFFFFFu, !(d3 > r2));

        #pragma unroll
        for (int t = 0; t < 4; t++) {
            unsigned m = bal[t];
            while (m && cnt < NBR) {
                idx[cnt++] = base + t * 32 + (__ffs(m) - 1);
                m &= m - 1;
            }
        }
        if (cnt >= NBR) break;
    }

    if (cnt < NBR) {                 // rare far-from-origin query -> kernel 2
        if (lane == 0) g_hard[warp] = 1;
        return;
    }
    if (lane == 0) g_hard[warp] = 0;

    // gather + max
    const float* fb = feat + (size_t)b * NN * CC;
    const float4* __restrict__ f0 = (const float4*)(fb + (size_t)idx[0] * CC);
    const float4* __restrict__ f1 = (const float4*)(fb + (size_t)idx[1] * CC);
    const float4* __restrict__ f2 = (const float4*)(fb + (size_t)idx[2] * CC);
    const float4* __restrict__ f3 = (const float4*)(fb + (size_t)idx[3] * CC);
    float4* __restrict__ fo = (float4*)(outF + ((size_t)b * POOLN + s) * CC);

    #pragma unroll
    for (int j = 0; j < CC / 128; j++) {
        const int c = lane + j * 32;
        float4 a = f0[c];
        const float4 v1 = f1[c], v2 = f2[c], v3 = f3[c];
        a.x = fmaxf(fmaxf(a.x, v1.x), fmaxf(v2.x, v3.x));
        a.y = fmaxf(fmaxf(a.y, v1.y), fmaxf(v2.y, v3.y));
        a.z = fmaxf(fmaxf(a.z, v1.z), fmaxf(v2.z, v3.z));
        a.w = fmaxf(fmaxf(a.w, v1.w), fmaxf(v2.w, v3.w));
        fo[c] = a;
    }
}

// ------------- Kernel 2: block per hard query, cooperative full scan -------------
__global__ __launch_bounds__(256)
void pool_hard_kernel(const float* __restrict__ feat,
                      const int*   __restrict__ radius_raw,
                      const int*   __restrict__ sample_idx,
                      float* __restrict__ outF)
{
    const int qid = blockIdx.x;             // 0 .. BB*POOLN-1
    if (!g_hard[qid]) return;

    const int b = qid / POOLN;
    const int s = qid - b * POOLN;
    const int t = threadIdx.x;               // 0..255, owns indices [t*32, t*32+32)
    const int lane = t & 31;
    const int wid  = t >> 5;

    __shared__ int s_wsum[8];
    __shared__ int s_idx[NBR];
    __shared__ int s_total;

    const int n = sample_idx[s];
    const float radius = decode_radius(radius_raw);
    const float r2 = radius * radius;

    const float4* __restrict__ pb = g_pack + b * NN;
    const float4 q = pb[n];
    const float qx = q.x, qy = q.y, qz = q.z;
    const float sqn = qx * qx + qy * qy + qz * qz;

    // build qualify mask over this thread's 32 contiguous points (MLP=8)
    unsigned mask = 0;
    const float4* __restrict__ base = pb + t * 32;
    #pragma unroll
    for (int j0 = 0; j0 < 32; j0 += 8) {
        float4 p[8];
        #pragma unroll
        for (int j = 0; j < 8; j++) p[j] = base[j0 + j];
        #pragma unroll
        for (int j = 0; j < 8; j++) {
            const float d = -2.0f*(p[j].x*qx + p[j].y*qy + p[j].z*qz) + sqn
                            + (p[j].x*p[j].x + p[j].y*p[j].y + p[j].z*p[j].z);
            mask |= ((unsigned)(!(d > r2))) << (j0 + j);
        }
    }

    // block-wide exclusive prefix of popcounts (ascending thread order = ascending index order)
    const int c = __popc(mask);
    int x = c;
    #pragma unroll
    for (int o = 1; o < 32; o <<= 1) {
        const int y = __shfl_up_sync(0xFFFFFFFFu, x, o);
        if (lane >= o) x += y;
    }
    if (lane == 31) s_wsum[wid] = x;
    __syncthreads();
    if (t == 0) {
        int acc = 0;
        #pragma unroll
        for (int w = 0; w < 8; w++) { const int v = s_wsum[w]; s_wsum[w] = acc; acc += v; }
        s_total = acc;
    }
    __syncthreads();
    const int pre = s_wsum[wid] + x - c;     // qualifiers strictly before this thread

    if (mask && pre < NBR) {
        unsigned m = mask;
        int p = pre;
        while (m && p < NBR) {
            s_idx[p++] = t * 32 + (__ffs(m) - 1);
            m &= m - 1;
        }
    }
    __syncthreads();
    if (t == 0) {
        const int tot = s_total < NBR ? s_total : NBR;  // tot >= 1 (self qualifies)
        for (int k = tot; k < NBR; k++) s_idx[k] = s_idx[0];
    }
    __syncthreads();

    // gather + max with 64 threads (64 float4 columns)
    if (t < CC / 4) {
        const float* fb = feat + (size_t)b * NN * CC;
        const float4 a0 = ((const float4*)(fb + (size_t)s_idx[0] * CC))[t];
        const float4 a1 = ((const float4*)(fb + (size_t)s_idx[1] * CC))[t];
        const float4 a2 = ((const float4*)(fb + (size_t)s_idx[2] * CC))[t];
        const float4 a3 = ((const float4*)(fb + (size_t)s_idx[3] * CC))[t];
        float4 r;
        r.x = fmaxf(fmaxf(a0.x, a1.x), fmaxf(a2.x, a3.x));
        r.y = fmaxf(fmaxf(a0.y, a1.y), fmaxf(a2.y, a3.y));
        r.z = fmaxf(fmaxf(a0.z, a1.z), fmaxf(a2.z, a3.z));
        r.w = fmaxf(fmaxf(a0.w, a1.w), fmaxf(a2.w, a3.w));
        ((float4*)(outF + ((size_t)b * POOLN + s) * CC))[t] = r;
    }
}

extern "C" void kernel_launch(void* const* d_in, const int* in_sizes, int n_in,
                              void* d_out, int out_size)
{
    const float* verts      = (const float*)d_in[0];
    const float* feat       = (const float*)d_in[1];
    const int*   radius_raw = (const int*)  d_in[2];
    const int*   sample_idx = (const int*)  d_in[3];

    float* outV = (float*)d_out;
    float* outF = (float*)d_out + (size_t)BB * POOLN * 3;

    pack_kernel<<<(BB * NN + 255) / 256, 256>>>(verts);

    const int total_warps = BB * POOLN;                  // 8192
    pool_easy_kernel<<<(total_warps * 32 + 255) / 256, 256>>>(feat, radius_raw,
                                                              sample_idx, outV, outF);
    pool_hard_kernel<<<BB * POOLN, 256>>>(feat, radius_raw, sample_idx, outF);
}

// round 4
// speedup vs baseline: 2.8506x; 1.5793x over previous
#include <cuda_runtime.h>
#include <cuda_bf16.h>

#define BB     4
#define NN     8192
#define CC     256
#define POOLN  2048
#define NBR    4
#define TILE_PTS   1024                  // smem tile: first 1024 points of the batch
#define TILE_FLOATS (TILE_PTS * 3)       // 3072 floats = 12 KB
#define QPB    8                         // queries (warps) per block

__device__ int g_hard_list[BB * POOLN];
__device__ int g_hard_count;

__device__ __forceinline__ float decode_radius(const int* radius_raw)
{
    const unsigned rv = (unsigned)__ldg(radius_raw);
    return (rv & 0x7F800000u) ? __int_as_float((int)rv) : (float)(int)rv;
}

__global__ void reset_kernel()
{
    if (threadIdx.x == 0) g_hard_count = 0;
}

// ---------------- Easy pass: 8 queries per block, smem vertex tile ----------------
__global__ __launch_bounds__(256)
void pool_easy_kernel(const float* __restrict__ verts,
                      const float* __restrict__ feat,
                      const int*   __restrict__ radius_raw,
                      const int*   __restrict__ sample_idx,
                      float* __restrict__ outV,
                      float* __restrict__ outF)
{
    __shared__ float s_tile[TILE_FLOATS];   // raw (x,y,z)*1024 of this batch

    const int wid  = threadIdx.x >> 5;
    const int lane = threadIdx.x & 31;
    const int qid  = blockIdx.x * QPB + wid;         // 0 .. BB*POOLN-1
    const int b    = qid >> 11;                      // / POOLN (uniform per block)
    const int s    = qid & (POOLN - 1);

    // Cooperative tile load: 768 float4 slots, coalesced.
    {
        const float4* __restrict__ src =
            (const float4*)(verts + (size_t)b * NN * 3);
        float4* dst = (float4*)s_tile;
        #pragma unroll
        for (int i = 0; i < TILE_FLOATS / 4 / 256; i++)
            dst[threadIdx.x + 256 * i] = src[threadIdx.x + 256 * i];
    }

    const int n = sample_idx[s];
    const float* vb = verts + (size_t)b * NN * 3;
    const float qx = vb[n * 3 + 0];
    const float qy = vb[n * 3 + 1];
    const float qz = vb[n * 3 + 2];
    const float sqn = qx * qx + qy * qy + qz * qz;

    const float radius = decode_radius(radius_raw);
    const float r2 = radius * radius;

    // vertices_pool (always written here)
    if (lane < 3) {
        const float v = (lane == 0) ? qx : (lane == 1) ? qy : qz;
        outV[((size_t)b * POOLN + s) * 3 + lane] = v;
    }

    __syncthreads();

    // ---- scan smem tile, first NBR ascending qualifiers ----
    int idx[NBR];
    int cnt = 0;
    #pragma unroll
    for (int k = 0; k < NBR; k++) idx[k] = n;

    for (int base = 0; base < TILE_PTS; base += 128) {
        unsigned bal[4];
        #pragma unroll
        for (int t = 0; t < 4; t++) {
            const int p = base + t * 32 + lane;
            const float px = s_tile[3 * p + 0];
            const float py = s_tile[3 * p + 1];
            const float pz = s_tile[3 * p + 2];
            const float d = -2.0f * (px * qx + py * qy + pz * qz) + sqn
                            + (px * px + py * py + pz * pz);
            bal[t] = __ballot_sync(0xFFFFFFFFu, !(d > r2));
        }
        #pragma unroll
        for (int t = 0; t < 4; t++) {
            unsigned m = bal[t];
            while (m && cnt < NBR) {
                idx[cnt++] = base + t * 32 + (__ffs(m) - 1);
                m &= m - 1;
            }
        }
        if (cnt >= NBR) break;   // uniform (ballot-derived)
    }

    if (cnt < NBR) {             // rare: defer to hard pass
        if (lane == 0) {
            const int pos = atomicAdd(&g_hard_count, 1);
            g_hard_list[pos] = qid;
        }
        return;
    }

    // ---- gather 4 feature rows (float4), max, store ----
    const float* fb = feat + (size_t)b * NN * CC;
    const float4* __restrict__ f0 = (const float4*)(fb + (size_t)idx[0] * CC);
    const float4* __restrict__ f1 = (const float4*)(fb + (size_t)idx[1] * CC);
    const float4* __restrict__ f2 = (const float4*)(fb + (size_t)idx[2] * CC);
    const float4* __restrict__ f3 = (const float4*)(fb + (size_t)idx[3] * CC);
    float4* __restrict__ fo = (float4*)(outF + ((size_t)b * POOLN + s) * CC);

    #pragma unroll
    for (int j = 0; j < CC / 128; j++) {
        const int c = lane + j * 32;
        float4 a = f0[c];
        const float4 v1 = f1[c], v2 = f2[c], v3 = f3[c];
        a.x = fmaxf(fmaxf(a.x, v1.x), fmaxf(v2.x, v3.x));
        a.y = fmaxf(fmaxf(a.y, v1.y), fmaxf(v2.y, v3.y));
        a.z = fmaxf(fmaxf(a.z, v1.z), fmaxf(v2.z, v3.z));
        a.w = fmaxf(fmaxf(a.w, v1.w), fmaxf(v2.w, v3.w));
        fo[c] = a;
    }
}

// ---------------- Hard pass: block per flagged query, full N scan ----------------
__global__ __launch_bounds__(256)
void pool_hard_kernel(const float* __restrict__ verts,
                      const float* __restrict__ feat,
                      const int*   __restrict__ radius_raw,
                      const int*   __restrict__ sample_idx,
                      float* __restrict__ outF)
{
    const int nhard = g_hard_count;

    for (int it = blockIdx.x; it < nhard; it += gridDim.x) {
        const int qid = g_hard_list[it];
        const int b = qid >> 11;
        const int s = qid & (POOLN - 1);
        const int t = threadIdx.x;           // owns points [t*32, t*32+32)
        const int lane = t & 31;
        const int wid  = t >> 5;

        __shared__ int s_wsum[8];
        __shared__ int s_idx[NBR];
        __shared__ int s_total;

        const int n = sample_idx[s];
        const float radius = decode_radius(radius_raw);
        const float r2 = radius * radius;

        const float* vb = verts + (size_t)b * NN * 3;
        const float qx = vb[n * 3 + 0];
        const float qy = vb[n * 3 + 1];
        const float qz = vb[n * 3 + 2];
        const float sqn = qx * qx + qy * qy + qz * qz;

        // qualify mask over this thread's 32 contiguous points (float4 loads, MLP)
        unsigned mask = 0;
        const float4* __restrict__ base4 = (const float4*)(vb + (size_t)t * 96);
        #pragma unroll
        for (int g = 0; g < 4; g++) {        // 8 points per group = 6 float4
            float4 v[6];
            #pragma unroll
            for (int u = 0; u < 6; u++) v[u] = base4[g * 6 + u];
            const float* f = (const float*)v;
            #pragma unroll
            for (int j = 0; j < 8; j++) {
                const float px = f[3 * j + 0];
                const float py = f[3 * j + 1];
                const float pz = f[3 * j + 2];
                const float d = -2.0f * (px * qx + py * qy + pz * qz) + sqn
                                + (px * px + py * py + pz * pz);
                mask |= ((unsigned)(!(d > r2))) << (g * 8 + j);
            }
        }

        // block-wide exclusive prefix over popcounts (thread order == index order)
        const int c = __popc(mask);
        int x = c;
        #pragma unroll
        for (int o = 1; o < 32; o <<= 1) {
            const int y = __shfl_up_sync(0xFFFFFFFFu, x, o);
            if (lane >= o) x += y;
        }
        if (lane == 31) s_wsum[wid] = x;
        __syncthreads();
        if (t == 0) {
            int acc = 0;
            #pragma unroll
            for (int w = 0; w < 8; w++) { const int v = s_wsum[w]; s_wsum[w] = acc; acc += v; }
            s_total = acc;
        }
        __syncthreads();
        const int pre = s_wsum[wid] + x - c;

        if (mask && pre < NBR) {
            unsigned m = mask;
            int p = pre;
            while (m && p < NBR) {
                s_idx[p++] = t * 32 + (__ffs(m) - 1);
                m &= m - 1;
            }
        }
        __syncthreads();
        if (t == 0) {
            const int tot = s_total < NBR ? s_total : NBR;   // >= 1 (self qualifies)
            for (int k = tot; k < NBR; k++) s_idx[k] = s_idx[0];
        }
        __syncthreads();

        if (t < CC / 4) {
            const float* fb = feat + (size_t)b * NN * CC;
            const float4 a0 = ((const float4*)(fb + (size_t)s_idx[0] * CC))[t];
            const float4 a1 = ((const float4*)(fb + (size_t)s_idx[1] * CC))[t];
            const float4 a2 = ((const float4*)(fb + (size_t)s_idx[2] * CC))[t];
            const float4 a3 = ((const float4*)(fb + (size_t)s_idx[3] * CC))[t];
            float4 r;
            r.x = fmaxf(fmaxf(a0.x, a1.x), fmaxf(a2.x, a3.x));
            r.y = fmaxf(fmaxf(a0.y, a1.y), fmaxf(a2.y, a3.y));
            r.z = fmaxf(fmaxf(a0.z, a1.z), fmaxf(a2.z, a3.z));
            r.w = fmaxf(fmaxf(a0.w, a1.w), fmaxf(a2.w, a3.w));
            ((float4*)(outF + ((size_t)b * POOLN + s) * CC))[t] = r;
        }
        __syncthreads();   // protect s_* reuse across loop iterations
    }
}

extern "C" void kernel_launch(void* const* d_in, const int* in_sizes, int n_in,
                              void* d_out, int out_size)
{
    const float* verts      = (const float*)d_in[0];
    const float* feat       = (const float*)d_in[1];
    const int*   radius_raw = (const int*)  d_in[2];
    const int*   sample_idx = (const int*)  d_in[3];

    float* outV = (float*)d_out;
    float* outF = (float*)d_out + (size_t)BB * POOLN * 3;

    reset_kernel<<<1, 32>>>();
    pool_easy_kernel<<<BB * POOLN / QPB, 256>>>(verts, feat, radius_raw,
                                                sample_idx, outV, outF);
    pool_hard_kernel<<<256, 256>>>(verts, feat, radius_raw, sample_idx, outF);
}